// round 4
// baseline (speedup 1.0000x reference)
#include <cuda_runtime.h>
#include <cstdint>

// ---------------------------------------------------------------------------
// LocallyGroupedAttn: mma.sync tf32 GEMMs (qkv, proj) + fp32 window attention.
// (tcgen05 is sm_103a-gated; harness PTX target is compute_103 -> legacy
//  mma.sync tensor path. __device__ scratch symbols referenced ONLY in device
//  code -- passing them from host was the R3 bug.)
// B=8, H=W=112, C=256, ws=7, nh=8, hd=32.
// ---------------------------------------------------------------------------

#define B_    8
#define H_    112
#define W_    112
#define C_    256
#define WS_   7
#define NH_   8
#define HD_   32
#define WS2_  49
#define BW_   (B_ * 16 * 16)     // 2048
#define M_    (BW_ * WS2_)       // 100352

__device__ float g_q[M_ * C_];
__device__ float g_k[M_ * C_];
__device__ float g_v[M_ * C_];
__device__ float g_o[M_ * C_];

__device__ __forceinline__ int token_of(int m) {
    int bw  = m / WS2_;
    int t   = m - bw * WS2_;
    int b   = bw >> 8;
    int win = bw & 255;
    int ty  = t / WS_;
    int tx  = t - ty * WS_;
    int y   = (win >> 4) * WS_ + ty;
    int x   = (win & 15) * WS_ + tx;
    return (b * H_ + y) * W_ + x;
}

__device__ __forceinline__ uint32_t f2tf32(float f) {
    uint32_t u;
    asm("cvt.rna.tf32.f32 %0, %1;" : "=r"(u) : "f"(f));
    return u;
}

// m16n8k8 tf32 MMA (row.col), fp32 accumulate, in-place C.
__device__ __forceinline__ void mma_tf32(float c[4], const uint32_t a[4], const uint32_t b[2]) {
    asm volatile(
        "mma.sync.aligned.m16n8k8.row.col.f32.tf32.tf32.f32 "
        "{%0,%1,%2,%3}, {%4,%5,%6,%7}, {%8,%9}, {%0,%1,%2,%3};"
        : "+f"(c[0]), "+f"(c[1]), "+f"(c[2]), "+f"(c[3])
        : "r"(a[0]), "r"(a[1]), "r"(a[2]), "r"(a[3]), "r"(b[0]), "r"(b[1]));
}

#define ASTRIDE 132   // 128 + 4 pad
#define BSTRIDE 68    // 64 + 4 pad

// ---------------------------------------------------------------------------
// GEMM: out[m][n] = sum_k A[m][k] * w[n][k] + bias[n]
// Block tile 128(m) x 64(n), BK=32, 256 threads (8 warps, 4m x 2n).
// MODE 0: A = x, rows gathered via token_of, outputs scattered to g_q/g_k/g_v.
// MODE 1: A = g_o (device symbol), outputs scattered to token order in `out`.
// ---------------------------------------------------------------------------
template <int MODE>
__global__ __launch_bounds__(256) void mma_gemm(const float* __restrict__ A,
                                                const float* __restrict__ w,
                                                const float* __restrict__ bias,
                                                float* __restrict__ out) {
    __shared__ uint32_t As[32 * ASTRIDE];
    __shared__ uint32_t Bs[32 * BSTRIDE];
    __shared__ const float* rowp[128];

    const int tid    = threadIdx.x;
    const int lane   = tid & 31;
    const int wid    = tid >> 5;
    const int warp_m = wid & 3;    // 0..3  -> 32-row slab
    const int warp_n = wid >> 2;   // 0..1  -> 32-col slab
    const int q      = lane & 3;
    const int g      = lane >> 2;
    const int m0     = blockIdx.y * 128;
    const int n0     = blockIdx.x * 64;

    if (tid < 128) {
        const int m = m0 + tid;
        rowp[tid] = (MODE == 0) ? A + (size_t)token_of(m) * C_
                                : (const float*)g_o + (size_t)m * C_;
    }
    __syncthreads();

    float acc[2][4][4];
#pragma unroll
    for (int mt = 0; mt < 2; mt++)
#pragma unroll
        for (int nt = 0; nt < 4; nt++)
#pragma unroll
            for (int i = 0; i < 4; i++) acc[mt][nt][i] = 0.f;

    for (int k0 = 0; k0 < C_; k0 += 32) {
        // --- A tile: 128 rows x 32 k = 1024 float4, 4/thread. rows fastest. ---
#pragma unroll
        for (int l = 0; l < 4; l++) {
            const int idx = tid + l * 256;
            const int row = idx & 127;
            const int kc  = idx >> 7;          // 0..7 (4-float chunk)
            const float4 v = *(const float4*)(rowp[row] + k0 + kc * 4);
            uint32_t* p = As + (kc * 4) * ASTRIDE + row;
            p[0 * ASTRIDE] = f2tf32(v.x);
            p[1 * ASTRIDE] = f2tf32(v.y);
            p[2 * ASTRIDE] = f2tf32(v.z);
            p[3 * ASTRIDE] = f2tf32(v.w);
        }
        // --- B tile: 64 n x 32 k = 512 float4, 2/thread, transpose to Bs[k][n] ---
#pragma unroll
        for (int l = 0; l < 2; l++) {
            const int idx = tid + l * 256;
            const int n   = idx & 63;
            const int kc  = idx >> 6;          // 0..7
            const float4 v = *(const float4*)(w + (size_t)(n0 + n) * C_ + k0 + kc * 4);
            uint32_t* p = Bs + (kc * 4) * BSTRIDE + n;
            p[0 * BSTRIDE] = f2tf32(v.x);
            p[1 * BSTRIDE] = f2tf32(v.y);
            p[2 * BSTRIDE] = f2tf32(v.z);
            p[3 * BSTRIDE] = f2tf32(v.w);
        }
        __syncthreads();

#pragma unroll
        for (int ks = 0; ks < 4; ks++) {       // k sub-step of 8
            const uint32_t* Ab = As + (ks * 8 + q) * ASTRIDE;
            const uint32_t* Bb = Bs + (ks * 8 + q) * BSTRIDE;
            uint32_t af[2][4], bf[4][2];
#pragma unroll
            for (int mt = 0; mt < 2; mt++) {
                const int r0 = warp_m * 32 + mt * 16 + g;
                af[mt][0] = Ab[r0];
                af[mt][1] = Ab[r0 + 8];
                af[mt][2] = Ab[4 * ASTRIDE + r0];
                af[mt][3] = Ab[4 * ASTRIDE + r0 + 8];
            }
#pragma unroll
            for (int nt = 0; nt < 4; nt++) {
                const int c0 = warp_n * 32 + nt * 8 + g;
                bf[nt][0] = Bb[c0];
                bf[nt][1] = Bb[4 * BSTRIDE + c0];
            }
#pragma unroll
            for (int mt = 0; mt < 2; mt++)
#pragma unroll
                for (int nt = 0; nt < 4; nt++)
                    mma_tf32(acc[mt][nt], af[mt], bf[nt]);
        }
        __syncthreads();
    }

    // --- Epilogue: thread owns rows {base, base+8} x cols {nt*8 + 2q, +1} ---
#pragma unroll
    for (int mt = 0; mt < 2; mt++) {
#pragma unroll
        for (int rr = 0; rr < 2; rr++) {
            const int m = m0 + warp_m * 32 + mt * 16 + g + rr * 8;
            float* dst;
            size_t base;
            if (MODE == 0) {
                const int part = n0 >> 8;
                const int chn  = n0 & 255;
                dst  = (part == 0) ? g_q : (part == 1) ? g_k : g_v;
                base = (size_t)m * C_ + chn;
            } else {
                dst  = out;
                base = (size_t)token_of(m) * C_ + n0;
            }
#pragma unroll
            for (int nt = 0; nt < 4; nt++) {
                const int cl = warp_n * 32 + nt * 8 + 2 * q;
                float2 v;
                v.x = acc[mt][nt][rr * 2 + 0] + bias[n0 + cl];
                v.y = acc[mt][nt][rr * 2 + 1] + bias[n0 + cl + 1];
                *(float2*)(dst + base + (size_t)(MODE == 0 ? cl : cl)) = v;
            }
        }
    }
}

// ---------------------------------------------------------------------------
// Attention: one block per (window, head), fp32 (unchanged).
// ---------------------------------------------------------------------------
__global__ __launch_bounds__(256) void attn_kernel() {
    const int bwh = blockIdx.x;
    const int bw  = bwh >> 3;
    const int h   = bwh & 7;

    __shared__ float qs[52 * 33];
    __shared__ float ks[52 * 33];
    __shared__ float vs[52 * 33];
    __shared__ float S[52 * 53];

    const int tid = threadIdx.x;
    const size_t base = (size_t)bw * WS2_ * C_ + h * HD_;

    for (int idx = tid; idx < WS2_ * HD_; idx += 256) {
        int i = idx >> 5, d = idx & 31;
        qs[i * 33 + d] = g_q[base + (size_t)i * C_ + d];
        ks[i * 33 + d] = g_k[base + (size_t)i * C_ + d];
        vs[i * 33 + d] = g_v[base + (size_t)i * C_ + d];
    }
    for (int idx = tid; idx < 288; idx += 256) {
        int arr = idx / 96;
        int rem = idx - arr * 96;
        int off = (49 + (rem >> 5)) * 33 + (rem & 31);
        float* p = (arr == 0) ? qs : (arr == 1) ? ks : vs;
        p[off] = 0.f;
    }
    __syncthreads();

    const float scale = 0.17677669529663687f;
    if (tid < 169) {
        const int jt = tid % 13, it = tid / 13;
        const int i0 = it * 4, j0 = jt * 4;
        float acc[4][4];
#pragma unroll
        for (int r = 0; r < 4; r++)
#pragma unroll
            for (int c = 0; c < 4; c++) acc[r][c] = 0.f;
#pragma unroll
        for (int d = 0; d < HD_; d++) {
            float a[4], b[4];
#pragma unroll
            for (int r = 0; r < 4; r++) a[r] = qs[(i0 + r) * 33 + d];
#pragma unroll
            for (int c = 0; c < 4; c++) b[c] = ks[(j0 + c) * 33 + d];
#pragma unroll
            for (int r = 0; r < 4; r++)
#pragma unroll
                for (int c = 0; c < 4; c++) acc[r][c] = fmaf(a[r], b[c], acc[r][c]);
        }
#pragma unroll
        for (int r = 0; r < 4; r++)
#pragma unroll
            for (int c = 0; c < 4; c++) S[(i0 + r) * 53 + (j0 + c)] = acc[r][c] * scale;
    }
    __syncthreads();

    if (tid < WS2_) {
        float* rowp = S + tid * 53;
        float mx = rowp[0];
#pragma unroll
        for (int j = 1; j < WS2_; j++) mx = fmaxf(mx, rowp[j]);
        float sum = 0.f;
#pragma unroll
        for (int j = 0; j < WS2_; j++) {
            float e = __expf(rowp[j] - mx);
            rowp[j] = e;
            sum += e;
        }
        float inv = __frcp_rn(sum);
#pragma unroll
        for (int j = 0; j < WS2_; j++) rowp[j] *= inv;
    }
    __syncthreads();

    {
        const int txd = tid & 7;
        const int tyy = tid >> 3;
        if (tyy < 25) {
            const int d0 = txd * 4;
            float acc[2][4];
#pragma unroll
            for (int r = 0; r < 2; r++)
#pragma unroll
                for (int c = 0; c < 4; c++) acc[r][c] = 0.f;
#pragma unroll
            for (int j = 0; j < WS2_; j++) {
                float a0 = S[(tyy * 2 + 0) * 53 + j];
                float a1 = S[(tyy * 2 + 1) * 53 + j];
                float v0 = vs[j * 33 + d0 + 0];
                float v1 = vs[j * 33 + d0 + 1];
                float v2 = vs[j * 33 + d0 + 2];
                float v3 = vs[j * 33 + d0 + 3];
                acc[0][0] = fmaf(a0, v0, acc[0][0]);
                acc[0][1] = fmaf(a0, v1, acc[0][1]);
                acc[0][2] = fmaf(a0, v2, acc[0][2]);
                acc[0][3] = fmaf(a0, v3, acc[0][3]);
                acc[1][0] = fmaf(a1, v0, acc[1][0]);
                acc[1][1] = fmaf(a1, v1, acc[1][1]);
                acc[1][2] = fmaf(a1, v2, acc[1][2]);
                acc[1][3] = fmaf(a1, v3, acc[1][3]);
            }
#pragma unroll
            for (int r = 0; r < 2; r++) {
                int i = tyy * 2 + r;
                if (i < WS2_) {
                    float* o = g_o + (size_t)(bw * WS2_ + i) * C_ + h * HD_ + d0;
                    o[0] = acc[r][0];
                    o[1] = acc[r][1];
                    o[2] = acc[r][2];
                    o[3] = acc[r][3];
                }
            }
        }
    }
}

// ---------------------------------------------------------------------------
extern "C" void kernel_launch(void* const* d_in, const int* in_sizes, int n_in,
                              void* d_out, int out_size) {
    const float* x      = (const float*)d_in[0];
    const float* qkv_w  = (const float*)d_in[1];
    const float* qkv_b  = (const float*)d_in[2];
    const float* proj_w = (const float*)d_in[3];
    const float* proj_b = (const float*)d_in[4];
    float* out = (float*)d_out;

    // n-blocks fastest (grid.x) so all readers of an A slab are schedule-adjacent.
    mma_gemm<0><<<dim3(768 / 64, M_ / 128), 256>>>(x, qkv_w, qkv_b, nullptr);
    attn_kernel<<<BW_ * NH_, 256>>>();
    // MODE 1 reads g_o via the device symbol inside the kernel; A arg unused.
    mma_gemm<1><<<dim3(256 / 64, M_ / 128), 256>>>(nullptr, proj_w, proj_b, out);
}

// round 5
// speedup vs baseline: 2.9077x; 2.9077x over previous
#include <cuda_runtime.h>
#include <cstdint>

// ---------------------------------------------------------------------------
// LocallyGroupedAttn: pipelined mma.sync tf32 GEMMs + fp32 window attention.
// cp.async double-buffered 128x128 block tiles, warp tile 64x32,
// conflict-free stride-36 smem, cvt.rna.tf32 after fragment load.
// ---------------------------------------------------------------------------

#define B_    8
#define H_    112
#define W_    112
#define C_    256
#define WS_   7
#define NH_   8
#define HD_   32
#define WS2_  49
#define BW_   (B_ * 16 * 16)     // 2048
#define M_    (BW_ * WS2_)       // 100352

__device__ float g_q[M_ * C_];
__device__ float g_k[M_ * C_];
__device__ float g_v[M_ * C_];
__device__ float g_o[M_ * C_];

__device__ __forceinline__ int token_of(int m) {
    int bw  = m / WS2_;
    int t   = m - bw * WS2_;
    int b   = bw >> 8;
    int win = bw & 255;
    int ty  = t / WS_;
    int tx  = t - ty * WS_;
    int y   = (win >> 4) * WS_ + ty;
    int x   = (win & 15) * WS_ + tx;
    return (b * H_ + y) * W_ + x;
}

__device__ __forceinline__ uint32_t f2tf32(float f) {
    uint32_t u;
    asm("cvt.rna.tf32.f32 %0, %1;" : "=r"(u) : "f"(f));
    return u;
}

__device__ __forceinline__ uint32_t smem_u32(const void* p) {
    uint32_t a;
    asm("{ .reg .u64 t; cvta.to.shared.u64 t, %1; cvt.u32.u64 %0, t; }" : "=r"(a) : "l"(p));
    return a;
}

__device__ __forceinline__ void cp16(void* dst, const void* src) {
    asm volatile("cp.async.cg.shared.global [%0], [%1], 16;"
                 :: "r"(smem_u32(dst)), "l"(src));
}
#define CP_COMMIT() asm volatile("cp.async.commit_group;" ::: "memory")
#define CP_WAIT1()  asm volatile("cp.async.wait_group 1;" ::: "memory")

// m16n8k8 tf32 MMA (row.col), fp32 accumulate, in-place C.
__device__ __forceinline__ void mma_tf32(float c[4], const uint32_t a[4], const uint32_t b[2]) {
    asm volatile(
        "mma.sync.aligned.m16n8k8.row.col.f32.tf32.tf32.f32 "
        "{%0,%1,%2,%3}, {%4,%5,%6,%7}, {%8,%9}, {%0,%1,%2,%3};"
        : "+f"(c[0]), "+f"(c[1]), "+f"(c[2]), "+f"(c[3])
        : "r"(a[0]), "r"(a[1]), "r"(a[2]), "r"(a[3]), "r"(b[0]), "r"(b[1]));
}

#define TSTRIDE 36                       // 32 floats + 4 pad (16B-aligned rows)
#define STAGE_F (128 * TSTRIDE)          // floats per tile stage
#define SMEM_GEMM_BYTES (2 * STAGE_F * 4 * 2 + 128 * 8)   // As(2) + Bs(2) + rowp

// ---------------------------------------------------------------------------
// GEMM: out[m][n] = sum_k A[m][k] * w[n][k] + bias[n]
// Block 128m x 128n, BK=32, 8 warps (2m x 4n), warp tile 64x32.
// MODE 0: A = x gathered via token_of -> g_q/g_k/g_v.  MODE 1: g_o -> out.
// ---------------------------------------------------------------------------
template <int MODE>
__global__ __launch_bounds__(256, 2) void mma_gemm(const float* __restrict__ A,
                                                   const float* __restrict__ w,
                                                   const float* __restrict__ bias,
                                                   float* __restrict__ out) {
    extern __shared__ char dsm[];
    float* As = (float*)dsm;                         // [2][128][36]
    float* Bs = As + 2 * STAGE_F;                    // [2][128][36]
    const float** rowp = (const float**)(Bs + 2 * STAGE_F);

    const int tid    = threadIdx.x;
    const int lane   = tid & 31;
    const int wid    = tid >> 5;
    const int warp_m = wid & 1;     // 64-row slab
    const int warp_n = wid >> 1;    // 32-col slab
    const int q      = lane & 3;
    const int g      = lane >> 2;
    const int n0     = blockIdx.x * 128;
    const int m0     = blockIdx.y * 128;

    if (tid < 128) {
        const int m = m0 + tid;
        rowp[tid] = (MODE == 0) ? A + (size_t)token_of(m) * C_
                                : (const float*)g_o + (size_t)m * C_;
    }
    __syncthreads();

    // issue stage st loads for k-offset k0 (A:128x32, B:128x32; 16B chunks)
    auto issue = [&](int st, int k0) {
        float* Ad = As + st * STAGE_F;
        float* Bd = Bs + st * STAGE_F;
#pragma unroll
        for (int l = 0; l < 4; l++) {
            const int id  = tid + l * 256;           // 0..1023
            const int row = id >> 3;
            const int c   = id & 7;
            cp16(Ad + row * TSTRIDE + c * 4, rowp[row] + k0 + c * 4);
            cp16(Bd + row * TSTRIDE + c * 4, w + (size_t)(n0 + row) * C_ + k0 + c * 4);
        }
    };

    float acc[4][4][4];
#pragma unroll
    for (int mt = 0; mt < 4; mt++)
#pragma unroll
        for (int nt = 0; nt < 4; nt++)
#pragma unroll
            for (int i = 0; i < 4; i++) acc[mt][nt][i] = 0.f;

    issue(0, 0);  CP_COMMIT();
    issue(1, 32); CP_COMMIT();

    for (int it = 0; it < 8; it++) {
        CP_WAIT1();
        __syncthreads();
        const float* Asl = As + (it & 1) * STAGE_F;
        const float* Bsl = Bs + (it & 1) * STAGE_F;
#pragma unroll
        for (int ks = 0; ks < 4; ks++) {
            const int kb = ks * 8;
            uint32_t af[4][4], bf[4][2];
#pragma unroll
            for (int mt = 0; mt < 4; mt++) {
                const int r0 = warp_m * 64 + mt * 16 + g;
                af[mt][0] = f2tf32(Asl[(r0    ) * TSTRIDE + kb + q]);
                af[mt][1] = f2tf32(Asl[(r0 + 8) * TSTRIDE + kb + q]);
                af[mt][2] = f2tf32(Asl[(r0    ) * TSTRIDE + kb + q + 4]);
                af[mt][3] = f2tf32(Asl[(r0 + 8) * TSTRIDE + kb + q + 4]);
            }
#pragma unroll
            for (int nt = 0; nt < 4; nt++) {
                const int c0 = warp_n * 32 + nt * 8 + g;
                bf[nt][0] = f2tf32(Bsl[c0 * TSTRIDE + kb + q]);
                bf[nt][1] = f2tf32(Bsl[c0 * TSTRIDE + kb + q + 4]);
            }
#pragma unroll
            for (int mt = 0; mt < 4; mt++)
#pragma unroll
                for (int nt = 0; nt < 4; nt++)
                    mma_tf32(acc[mt][nt], af[mt], bf[nt]);
        }
        __syncthreads();
        const int kn = (it + 2) * 32;
        if (kn < 256) issue(it & 1, kn);
        CP_COMMIT();
    }

    // Epilogue
#pragma unroll
    for (int mt = 0; mt < 4; mt++) {
#pragma unroll
        for (int rr = 0; rr < 2; rr++) {
            const int m = m0 + warp_m * 64 + mt * 16 + g + rr * 8;
            float* dst;
            size_t base;
            if (MODE == 0) {
                const int part = n0 >> 8;
                const int chn  = n0 & 255;
                dst  = (part == 0) ? g_q : (part == 1) ? g_k : g_v;
                base = (size_t)m * C_ + chn;
            } else {
                dst  = out;
                base = (size_t)token_of(m) * C_ + n0;
            }
#pragma unroll
            for (int nt = 0; nt < 4; nt++) {
                const int cl = warp_n * 32 + nt * 8 + 2 * q;
                float2 v;
                v.x = acc[mt][nt][rr * 2 + 0] + bias[n0 + cl];
                v.y = acc[mt][nt][rr * 2 + 1] + bias[n0 + cl + 1];
                *(float2*)(dst + base + cl) = v;
            }
        }
    }
}

// ---------------------------------------------------------------------------
// Attention: one block per (window, head). stride-36 smem, float4 paths.
// ---------------------------------------------------------------------------
__global__ __launch_bounds__(256) void attn_kernel() {
    const int bwh = blockIdx.x;
    const int bw  = bwh >> 3;
    const int h   = bwh & 7;

    __shared__ float qs[52 * 36];
    __shared__ float ks[52 * 36];
    __shared__ float vs[52 * 36];
    __shared__ float S[52 * 53];

    const int tid = threadIdx.x;
    const size_t base = (size_t)bw * WS2_ * C_ + h * HD_;

    for (int idx = tid; idx < WS2_ * 8; idx += 256) {   // 392 float4 per array
        const int i = idx >> 3, c = (idx & 7) * 4;
        *(float4*)&qs[i * 36 + c] = *(const float4*)(g_q + base + (size_t)i * C_ + c);
        *(float4*)&ks[i * 36 + c] = *(const float4*)(g_k + base + (size_t)i * C_ + c);
        *(float4*)&vs[i * 36 + c] = *(const float4*)(g_v + base + (size_t)i * C_ + c);
    }
    // zero padded rows 49..51
    if (tid < 72) {
        const int arr = tid / 24;
        const int rem = tid % 24;
        const int off = (49 + rem / 8) * 36 + (rem & 7) * 4;
        float* p = (arr == 0) ? qs : (arr == 1) ? ks : vs;
        *(float4*)&p[off] = make_float4(0.f, 0.f, 0.f, 0.f);
    }
    __syncthreads();

    // --- S = Q K^T * scale : 13x13 thread tiles of 4x4, float4 over d ---
    const float scale = 0.17677669529663687f;
    if (tid < 169) {
        const int jt = tid % 13, it = tid / 13;
        const int i0 = it * 4, j0 = jt * 4;
        float acc[4][4];
#pragma unroll
        for (int r = 0; r < 4; r++)
#pragma unroll
            for (int c = 0; c < 4; c++) acc[r][c] = 0.f;
#pragma unroll
        for (int dq = 0; dq < 8; dq++) {
            float4 a4[4], b4[4];
#pragma unroll
            for (int r = 0; r < 4; r++) a4[r] = *(const float4*)&qs[(i0 + r) * 36 + dq * 4];
#pragma unroll
            for (int c = 0; c < 4; c++) b4[c] = *(const float4*)&ks[(j0 + c) * 36 + dq * 4];
#pragma unroll
            for (int r = 0; r < 4; r++)
#pragma unroll
                for (int c = 0; c < 4; c++) {
                    acc[r][c] = fmaf(a4[r].x, b4[c].x, acc[r][c]);
                    acc[r][c] = fmaf(a4[r].y, b4[c].y, acc[r][c]);
                    acc[r][c] = fmaf(a4[r].z, b4[c].z, acc[r][c]);
                    acc[r][c] = fmaf(a4[r].w, b4[c].w, acc[r][c]);
                }
        }
#pragma unroll
        for (int r = 0; r < 4; r++)
#pragma unroll
            for (int c = 0; c < 4; c++) S[(i0 + r) * 53 + (j0 + c)] = acc[r][c] * scale;
    }
    __syncthreads();

    // --- softmax rows 0..48 ---
    if (tid < WS2_) {
        float* rowp = S + tid * 53;
        float mx = rowp[0];
#pragma unroll
        for (int j = 1; j < WS2_; j++) mx = fmaxf(mx, rowp[j]);
        float sum = 0.f;
#pragma unroll
        for (int j = 0; j < WS2_; j++) {
            float e = __expf(rowp[j] - mx);
            rowp[j] = e;
            sum += e;
        }
        float inv = __frcp_rn(sum);
#pragma unroll
        for (int j = 0; j < WS2_; j++) rowp[j] *= inv;
    }
    __syncthreads();

    // --- O = P V : 2 rows x 4 d per thread ---
    {
        const int txd = tid & 7;
        const int tyy = tid >> 3;
        if (tyy < 25) {
            const int d0 = txd * 4;
            float acc[2][4];
#pragma unroll
            for (int r = 0; r < 2; r++)
#pragma unroll
                for (int c = 0; c < 4; c++) acc[r][c] = 0.f;
#pragma unroll
            for (int j = 0; j < WS2_; j++) {
                const float a0 = S[(tyy * 2 + 0) * 53 + j];
                const float a1 = S[(tyy * 2 + 1) * 53 + j];
                const float4 v4 = *(const float4*)&vs[j * 36 + d0];
                acc[0][0] = fmaf(a0, v4.x, acc[0][0]);
                acc[0][1] = fmaf(a0, v4.y, acc[0][1]);
                acc[0][2] = fmaf(a0, v4.z, acc[0][2]);
                acc[0][3] = fmaf(a0, v4.w, acc[0][3]);
                acc[1][0] = fmaf(a1, v4.x, acc[1][0]);
                acc[1][1] = fmaf(a1, v4.y, acc[1][1]);
                acc[1][2] = fmaf(a1, v4.z, acc[1][2]);
                acc[1][3] = fmaf(a1, v4.w, acc[1][3]);
            }
#pragma unroll
            for (int r = 0; r < 2; r++) {
                const int i = tyy * 2 + r;
                if (i < WS2_) {
                    float4 o4 = make_float4(acc[r][0], acc[r][1], acc[r][2], acc[r][3]);
                    *(float4*)(g_o + (size_t)(bw * WS2_ + i) * C_ + h * HD_ + d0) = o4;
                }
            }
        }
    }
}

// ---------------------------------------------------------------------------
extern "C" void kernel_launch(void* const* d_in, const int* in_sizes, int n_in,
                              void* d_out, int out_size) {
    const float* x      = (const float*)d_in[0];
    const float* qkv_w  = (const float*)d_in[1];
    const float* qkv_b  = (const float*)d_in[2];
    const float* proj_w = (const float*)d_in[3];
    const float* proj_b = (const float*)d_in[4];
    float* out = (float*)d_out;

    cudaFuncSetAttribute(mma_gemm<0>, cudaFuncAttributeMaxDynamicSharedMemorySize, SMEM_GEMM_BYTES);
    cudaFuncSetAttribute(mma_gemm<1>, cudaFuncAttributeMaxDynamicSharedMemorySize, SMEM_GEMM_BYTES);

    // n-blocks fastest (grid.x): A-tile re-readers are schedule-adjacent (L2 hits).
    mma_gemm<0><<<dim3(768 / 128, M_ / 128), 256, SMEM_GEMM_BYTES>>>(x, qkv_w, qkv_b, nullptr);
    attn_kernel<<<BW_ * NH_, 256>>>();
    mma_gemm<1><<<dim3(256 / 128, M_ / 128), 256, SMEM_GEMM_BYTES>>>(nullptr, proj_w, proj_b, out);
}